// round 9
// baseline (speedup 1.0000x reference)
#include <cuda_runtime.h>
#include <math.h>

// Problem dims (fixed)
#define BQ 8
#define SQ 2048
#define DQ 512
#define IQ 2048
#define MQ (BQ * SQ)            // 16384
#define BI (BQ * IQ)            // 16384

// GEMM tiling
#define BM 128
#define BN 64
#define BK 32

// Interleaved scratch: [(s*BQ+b)*IQ + i] -> (a, c) pairs
__device__ float g_AC[(size_t)MQ * IQ * 2];

__device__ __forceinline__ unsigned f2tf32(float f) {
    unsigned u;
    asm("cvt.rna.tf32.f32 %0, %1;" : "=r"(u) : "f"(f));
    return u;
}

__device__ __forceinline__ float sigmoidf_fast(float v) {
    return 1.0f / (1.0f + __expf(-v));
}

__device__ __forceinline__ void mma_tf32(float c[4], const unsigned a[4], const unsigned b[2]) {
    asm volatile(
        "mma.sync.aligned.m16n8k8.row.col.f32.tf32.tf32.f32 "
        "{%0,%1,%2,%3}, {%4,%5,%6,%7}, {%8,%9}, {%0,%1,%2,%3};\n"
        : "+f"(c[0]), "+f"(c[1]), "+f"(c[2]), "+f"(c[3])
        : "r"(a[0]), "r"(a[1]), "r"(a[2]), "r"(a[3]), "r"(b[0]), "r"(b[1]));
}

// ---------------------------------------------------------------------------
// Dual-projection tf32 tensor-core GEMM + fused gate epilogue.
//
// Fragment-friendly permuted smem layouts:
//  A:  xs[kk][g][r][slot][e]  (4*8*8*4*4 = 4096 u32).  For thread (r,cq) and
//      m-group g, the 4 A-fragment operands for one m16n8k8 live contiguously
//      at slot = cq ^ (r&3)  (XOR-swizzle cuts STS bank conflicts).
//      e = h + 2q encodes (row+8h, col+4q).
//  B:  ws[kk][wn][r] rows of 36 u32 (stride padded 32->36 for conflict-free
//      LDS.128); within a row: [cq][nt][q] so each (kk,proj) fragment set for
//      all 4 nt is two contiguous LDS.128.
// ---------------------------------------------------------------------------
__global__ __launch_bounds__(256)
void gemm_gate_kernel(const float* __restrict__ x,
                      const float* __restrict__ Wa,
                      const float* __restrict__ ba,
                      const float* __restrict__ Wi,
                      const float* __restrict__ bi,
                      const float* __restrict__ gate)
{
    __shared__ unsigned xs [4096];   // 16 KB
    __shared__ unsigned was[2304];   //  9 KB
    __shared__ unsigned wis[2304];   //  9 KB

    const int tid    = threadIdx.x;
    const int wid    = tid >> 5;
    const int lane   = tid & 31;
    const int warp_m = wid & 3;       // 4 warps over M (4*32 = 128)
    const int warp_n = wid >> 2;      // 2 warps over N (2*32 = 64)
    const int r      = lane >> 2;     // 0..7
    const int cq     = lane & 3;      // 0..3
    const int m0     = blockIdx.y * BM;
    const int n0     = blockIdx.x * BN;

    float acc_a[2][4][4];
    float acc_i[2][4][4];
#pragma unroll
    for (int mt = 0; mt < 2; mt++)
#pragma unroll
        for (int nt = 0; nt < 4; nt++)
#pragma unroll
            for (int e = 0; e < 4; e++) { acc_a[mt][nt][e] = 0.f; acc_i[mt][nt][e] = 0.f; }

    // ---- prefetch tile 0 into registers ----
    float4 px[4], pwa[2], pwi[2];
#pragma unroll
    for (int j = 0; j < 4; j++) {
        const int idx = tid + j * 256;          // 0..1023: 128 rows x 8 float4
        px[j] = *(const float4*)(x + (size_t)(m0 + (idx >> 3)) * DQ + (idx & 7) * 4);
    }
#pragma unroll
    for (int j = 0; j < 2; j++) {
        const int idx = tid + j * 256;          // 0..511: 64 rows x 8 float4
        pwa[j] = *(const float4*)(Wa + (size_t)(n0 + (idx >> 3)) * DQ + (idx & 7) * 4);
        pwi[j] = *(const float4*)(Wi + (size_t)(n0 + (idx >> 3)) * DQ + (idx & 7) * 4);
    }

    for (int kt = 0; kt < DQ; kt += BK) {
        // ---- commit prefetched regs to permuted smem (rna tf32 rounding) ----
#pragma unroll
        for (int j = 0; j < 4; j++) {
            const int idx = tid + j * 256;
            const int row = idx >> 3, f4 = idx & 7;
            const int kk = f4 >> 1, q = f4 & 1;
            const int g = row >> 4, h = (row >> 3) & 1, rr = row & 7;
            const int r3 = rr & 3;
            unsigned* p = &xs[((kk * 8 + g) * 8 + rr) * 16 + h + 2 * q];
            p[(0 ^ r3) * 4] = f2tf32(px[j].x);
            p[(1 ^ r3) * 4] = f2tf32(px[j].y);
            p[(2 ^ r3) * 4] = f2tf32(px[j].z);
            p[(3 ^ r3) * 4] = f2tf32(px[j].w);
        }
#pragma unroll
        for (int j = 0; j < 2; j++) {
            const int idx = tid + j * 256;
            const int row = idx >> 3, f4 = idx & 7;
            const int kk = f4 >> 1, q = f4 & 1;
            const int wn = row >> 5, nt = (row >> 3) & 3, rr = row & 7;
            const int base = ((kk * 2 + wn) * 8 + rr) * 36 + nt * 2 + q;
            was[base +  0] = f2tf32(pwa[j].x);
            was[base +  8] = f2tf32(pwa[j].y);
            was[base + 16] = f2tf32(pwa[j].z);
            was[base + 24] = f2tf32(pwa[j].w);
            wis[base +  0] = f2tf32(pwi[j].x);
            wis[base +  8] = f2tf32(pwi[j].y);
            wis[base + 16] = f2tf32(pwi[j].z);
            wis[base + 24] = f2tf32(pwi[j].w);
        }
        __syncthreads();

        // ---- issue next tile's global loads (latency hidden by MMA phase) ----
        const int ktn = kt + BK;
        if (ktn < DQ) {
#pragma unroll
            for (int j = 0; j < 4; j++) {
                const int idx = tid + j * 256;
                px[j] = *(const float4*)(x + (size_t)(m0 + (idx >> 3)) * DQ + ktn + (idx & 7) * 4);
            }
#pragma unroll
            for (int j = 0; j < 2; j++) {
                const int idx = tid + j * 256;
                pwa[j] = *(const float4*)(Wa + (size_t)(n0 + (idx >> 3)) * DQ + ktn + (idx & 7) * 4);
                pwi[j] = *(const float4*)(Wi + (size_t)(n0 + (idx >> 3)) * DQ + ktn + (idx & 7) * 4);
            }
        }

        // ---- MMA phase: 4 k-steps of 8 ----
        const int slot = (cq ^ (r & 3)) * 4;
#pragma unroll
        for (int kk = 0; kk < 4; kk++) {
            unsigned afr[2][4];
#pragma unroll
            for (int mt = 0; mt < 2; mt++) {
                const int g = warp_m * 2 + mt;
                uint4 av = *(const uint4*)&xs[((kk * 8 + g) * 8 + r) * 16 + slot];
                afr[mt][0] = av.x; afr[mt][1] = av.y; afr[mt][2] = av.z; afr[mt][3] = av.w;
            }
            const int wb = ((kk * 2 + warp_n) * 8 + r) * 36 + cq * 8;
            uint4 a01 = *(const uint4*)&was[wb];
            uint4 a23 = *(const uint4*)&was[wb + 4];
            uint4 i01 = *(const uint4*)&wis[wb];
            uint4 i23 = *(const uint4*)&wis[wb + 4];
            unsigned bfa[4][2] = {{a01.x, a01.y}, {a01.z, a01.w}, {a23.x, a23.y}, {a23.z, a23.w}};
            unsigned bfi[4][2] = {{i01.x, i01.y}, {i01.z, i01.w}, {i23.x, i23.y}, {i23.z, i23.w}};
#pragma unroll
            for (int mt = 0; mt < 2; mt++)
#pragma unroll
                for (int nt = 0; nt < 4; nt++) {
                    mma_tf32(acc_a[mt][nt], afr[mt], bfa[nt]);
                    mma_tf32(acc_i[mt][nt], afr[mt], bfi[nt]);
                }
        }
        __syncthreads();
    }

    // ---- fused gate epilogue ----
    const float LN3 = 1.0986122886681098f;
#pragma unroll
    for (int nt = 0; nt < 4; nt++) {
        const int ich0 = n0 + warp_n * 32 + nt * 8 + 2 * cq;
        const float ba0 = __ldg(ba + ich0),     ba1 = __ldg(ba + ich0 + 1);
        const float bi0 = __ldg(bi + ich0),     bi1 = __ldg(bi + ich0 + 1);
        const float al0 = sigmoidf_fast(__ldg(gate + ich0));
        const float al1 = sigmoidf_fast(__ldg(gate + ich0 + 1));
#pragma unroll
        for (int mt = 0; mt < 2; mt++) {
#pragma unroll
            for (int ro = 0; ro < 2; ro++) {
                const int m  = m0 + warp_m * 32 + mt * 16 + r + ro * 8;
                const int bb = m >> 11;
                const int ss = m & (SQ - 1);
                const int ci = ro * 2;
                float pa0 = acc_a[mt][nt][ci]     + ba0;
                float pa1 = acc_a[mt][nt][ci + 1] + ba1;
                float pi0 = acc_i[mt][nt][ci]     + bi0;
                float pi1 = acc_i[mt][nt][ci + 1] + bi1;
                float a0 = al0 * __expf(-sigmoidf_fast(pa0) * LN3);
                float a1 = al1 * __expf(-sigmoidf_fast(pa1) * LN3);
                float c0 = sqrtf(fmaxf(1.0f - a0 * a0, 0.0f)) * sigmoidf_fast(pi0) * pi0;
                float c1 = sqrtf(fmaxf(1.0f - a1 * a1, 0.0f)) * sigmoidf_fast(pi1) * pi1;
                float4 st = make_float4(a0, c0, a1, c1);
                size_t idx = (((size_t)ss * BQ + bb) * IQ + ich0) * 2;
                *(float4*)(g_AC + idx) = st;
            }
        }
    }
}

// Sequential scan: h[t] = a*h + c. Double-buffered batches of U steps keep
// ~32 loads in flight per thread; plain loads (no cache hints).
#define SCAN_U 16
__global__ __launch_bounds__(128)
void scan_kernel(float* __restrict__ out)
{
    const int tid = blockIdx.x * blockDim.x + threadIdx.x;  // 0..BI-1
    const int b = tid >> 11;
    const int i = tid & (IQ - 1);
    const float2* ac = ((const float2*)g_AC) + tid;
    float* o = out + (size_t)b * SQ * IQ + i;

    float2 buf[SCAN_U];
#pragma unroll
    for (int u = 0; u < SCAN_U; u++) buf[u] = ac[(size_t)u * BI];

    float h = 0.0f;
    for (int t0 = 0; t0 < SQ; t0 += SCAN_U) {
        float2 nxt[SCAN_U];
        const int tn = t0 + SCAN_U;
        if (tn < SQ) {
#pragma unroll
            for (int u = 0; u < SCAN_U; u++) nxt[u] = ac[(size_t)(tn + u) * BI];
        }
#pragma unroll
        for (int u = 0; u < SCAN_U; u++) {
            h = fmaf(buf[u].x, h, buf[u].y);
            o[(size_t)(t0 + u) * IQ] = h;
        }
#pragma unroll
        for (int u = 0; u < SCAN_U; u++) buf[u] = nxt[u];
    }
}

extern "C" void kernel_launch(void* const* d_in, const int* in_sizes, int n_in,
                              void* d_out, int out_size)
{
    const float* x    = (const float*)d_in[0];
    const float* Wa   = (const float*)d_in[1];
    const float* ba   = (const float*)d_in[2];
    const float* Wi   = (const float*)d_in[3];
    const float* bi   = (const float*)d_in[4];
    const float* gate = (const float*)d_in[5];
    float* out = (float*)d_out;

    dim3 grid(IQ / BN, MQ / BM);   // (32, 128)
    gemm_gate_kernel<<<grid, 256>>>(x, Wa, ba, Wi, bi, gate);
    scan_kernel<<<BI / 128, 128>>>(out);
}

// round 10
// speedup vs baseline: 1.2298x; 1.2298x over previous
#include <cuda_runtime.h>
#include <math.h>

// Problem dims (fixed)
#define BQ 8
#define SQ 2048
#define DQ 512
#define IQ 2048
#define MQ (BQ * SQ)            // 16384
#define BI (BQ * IQ)            // 16384

// GEMM tiling
#define BM 128
#define BN 64
#define BK 16
#define XS_STRIDE 20
#define WS_STRIDE 20

// Interleaved scratch: [(s*BQ+b)*IQ + i] -> (a, c) pairs
__device__ float g_AC[(size_t)MQ * IQ * 2];

__device__ __forceinline__ unsigned f2tf32(float f) {
    unsigned u;
    asm("cvt.rna.tf32.f32 %0, %1;" : "=r"(u) : "f"(f));
    return u;
}

__device__ __forceinline__ float sigmoidf_fast(float v) {
    return 1.0f / (1.0f + __expf(-v));
}

__device__ __forceinline__ void mma_tf32(float c[4], const unsigned a[4], const unsigned b[2]) {
    asm volatile(
        "mma.sync.aligned.m16n8k8.row.col.f32.tf32.tf32.f32 "
        "{%0,%1,%2,%3}, {%4,%5,%6,%7}, {%8,%9}, {%0,%1,%2,%3};\n"
        : "+f"(c[0]), "+f"(c[1]), "+f"(c[2]), "+f"(c[3])
        : "r"(a[0]), "r"(a[1]), "r"(a[2]), "r"(a[3]), "r"(b[0]), "r"(b[1]));
}

// Dual-projection tf32 tensor-core GEMM + fused gate epilogue.
// Round-6 structure (proven 2 CTAs/SM) + double-buffered smem so only ONE
// __syncthreads per k-tile: iteration k writes buffer k&1; a warp entering
// iteration k+1's store phase has passed iteration k's barrier, so the
// slowest warp is at worst in iteration k's MMA phase reading the OTHER buffer.
__global__ __launch_bounds__(256)
void gemm_gate_kernel(const float* __restrict__ x,
                      const float* __restrict__ Wa,
                      const float* __restrict__ ba,
                      const float* __restrict__ Wi,
                      const float* __restrict__ bi,
                      const float* __restrict__ gate)
{
    __shared__ unsigned xs [2][BM * XS_STRIDE];   // 2 x 10240 B
    __shared__ unsigned was[2][BN * WS_STRIDE];   // 2 x  5120 B
    __shared__ unsigned wis[2][BN * WS_STRIDE];   // 2 x  5120 B

    const int tid    = threadIdx.x;
    const int wid    = tid >> 5;
    const int lane   = tid & 31;
    const int warp_m = wid & 3;       // 4 warps over M (4*32 = 128)
    const int warp_n = wid >> 2;      // 2 warps over N (2*32 = 64)
    const int r      = lane >> 2;     // 0..7
    const int cq     = lane & 3;      // 0..3
    const int m0     = blockIdx.y * BM;
    const int n0     = blockIdx.x * BN;

    // per-thread load slots (same as round 6)
    const int xrow0 = tid >> 2;            // 0..63
    const int xrow1 = (tid + 256) >> 2;    // 64..127
    const int xkg   = tid & 3;
    const int wrow  = tid >> 2;
    const int wkg   = tid & 3;

    float acc_a[2][4][4];
    float acc_i[2][4][4];
#pragma unroll
    for (int mt = 0; mt < 2; mt++)
#pragma unroll
        for (int nt = 0; nt < 4; nt++)
#pragma unroll
            for (int e = 0; e < 4; e++) { acc_a[mt][nt][e] = 0.f; acc_i[mt][nt][e] = 0.f; }

    // prefetch tile 0
    float4 px0 = *(const float4*)(x  + (size_t)(m0 + xrow0) * DQ + xkg * 4);
    float4 px1 = *(const float4*)(x  + (size_t)(m0 + xrow1) * DQ + xkg * 4);
    float4 pwa = *(const float4*)(Wa + (size_t)(n0 + wrow)  * DQ + wkg * 4);
    float4 pwi = *(const float4*)(Wi + (size_t)(n0 + wrow)  * DQ + wkg * 4);

    for (int t = 0; t < DQ / BK; t++) {
        const int buf = t & 1;
        // ---- commit prefetched regs to smem buffer (rna tf32 rounding) ----
        {
            unsigned* p0 = &xs[buf][xrow0 * XS_STRIDE + xkg * 4];
            p0[0] = f2tf32(px0.x); p0[1] = f2tf32(px0.y); p0[2] = f2tf32(px0.z); p0[3] = f2tf32(px0.w);
            unsigned* p1 = &xs[buf][xrow1 * XS_STRIDE + xkg * 4];
            p1[0] = f2tf32(px1.x); p1[1] = f2tf32(px1.y); p1[2] = f2tf32(px1.z); p1[3] = f2tf32(px1.w);
            unsigned* pa_ = &was[buf][wrow * WS_STRIDE + wkg * 4];
            pa_[0] = f2tf32(pwa.x); pa_[1] = f2tf32(pwa.y); pa_[2] = f2tf32(pwa.z); pa_[3] = f2tf32(pwa.w);
            unsigned* pi_ = &wis[buf][wrow * WS_STRIDE + wkg * 4];
            pi_[0] = f2tf32(pwi.x); pi_[1] = f2tf32(pwi.y); pi_[2] = f2tf32(pwi.z); pi_[3] = f2tf32(pwi.w);
        }
        __syncthreads();

        // ---- issue next tile's global loads (hidden under MMA phase) ----
        const int ktn = (t + 1) * BK;
        if (ktn < DQ) {
            px0 = *(const float4*)(x  + (size_t)(m0 + xrow0) * DQ + ktn + xkg * 4);
            px1 = *(const float4*)(x  + (size_t)(m0 + xrow1) * DQ + ktn + xkg * 4);
            pwa = *(const float4*)(Wa + (size_t)(n0 + wrow)  * DQ + ktn + wkg * 4);
            pwi = *(const float4*)(Wi + (size_t)(n0 + wrow)  * DQ + ktn + wkg * 4);
        }

        // ---- MMA phase ----
#pragma unroll
        for (int kk = 0; kk < 2; kk++) {
            const int kb = kk * 8;
            unsigned afr[2][4];
#pragma unroll
            for (int mt = 0; mt < 2; mt++) {
                int base = warp_m * 32 + mt * 16;
                afr[mt][0] = xs[buf][(base + r)     * XS_STRIDE + kb + cq];
                afr[mt][1] = xs[buf][(base + r + 8) * XS_STRIDE + kb + cq];
                afr[mt][2] = xs[buf][(base + r)     * XS_STRIDE + kb + cq + 4];
                afr[mt][3] = xs[buf][(base + r + 8) * XS_STRIDE + kb + cq + 4];
            }
            unsigned bfa[4][2], bfi[4][2];
#pragma unroll
            for (int nt = 0; nt < 4; nt++) {
                int nb = warp_n * 32 + nt * 8 + r;
                bfa[nt][0] = was[buf][nb * WS_STRIDE + kb + cq];
                bfa[nt][1] = was[buf][nb * WS_STRIDE + kb + cq + 4];
                bfi[nt][0] = wis[buf][nb * WS_STRIDE + kb + cq];
                bfi[nt][1] = wis[buf][nb * WS_STRIDE + kb + cq + 4];
            }
#pragma unroll
            for (int mt = 0; mt < 2; mt++)
#pragma unroll
                for (int nt = 0; nt < 4; nt++) {
                    mma_tf32(acc_a[mt][nt], afr[mt], bfa[nt]);
                    mma_tf32(acc_i[mt][nt], afr[mt], bfi[nt]);
                }
        }
        // no trailing sync: next iteration writes the other buffer
    }

    // ---- fused gate epilogue ----
    const float LN3 = 1.0986122886681098f;
#pragma unroll
    for (int nt = 0; nt < 4; nt++) {
        const int ich0 = n0 + warp_n * 32 + nt * 8 + 2 * cq;
        const float ba0 = __ldg(ba + ich0),     ba1 = __ldg(ba + ich0 + 1);
        const float bi0 = __ldg(bi + ich0),     bi1 = __ldg(bi + ich0 + 1);
        const float al0 = sigmoidf_fast(__ldg(gate + ich0));
        const float al1 = sigmoidf_fast(__ldg(gate + ich0 + 1));
#pragma unroll
        for (int mt = 0; mt < 2; mt++) {
#pragma unroll
            for (int ro = 0; ro < 2; ro++) {
                const int m  = m0 + warp_m * 32 + mt * 16 + r + ro * 8;
                const int bb = m >> 11;
                const int ss = m & (SQ - 1);
                const int ci = ro * 2;
                float pa0 = acc_a[mt][nt][ci]     + ba0;
                float pa1 = acc_a[mt][nt][ci + 1] + ba1;
                float pi0 = acc_i[mt][nt][ci]     + bi0;
                float pi1 = acc_i[mt][nt][ci + 1] + bi1;
                float a0 = al0 * __expf(-sigmoidf_fast(pa0) * LN3);
                float a1 = al1 * __expf(-sigmoidf_fast(pa1) * LN3);
                float c0 = sqrtf(fmaxf(1.0f - a0 * a0, 0.0f)) * sigmoidf_fast(pi0) * pi0;
                float c1 = sqrtf(fmaxf(1.0f - a1 * a1, 0.0f)) * sigmoidf_fast(pi1) * pi1;
                float4 st = make_float4(a0, c0, a1, c1);
                size_t idx = (((size_t)ss * BQ + bb) * IQ + ich0) * 2;
                *(float4*)(g_AC + idx) = st;
            }
        }
    }
}

// Sequential scan: h[t] = a*h + c. Double-buffered batches of U steps keep
// ~32 loads in flight per thread; plain loads (no cache hints).
#define SCAN_U 16
__global__ __launch_bounds__(128)
void scan_kernel(float* __restrict__ out)
{
    const int tid = blockIdx.x * blockDim.x + threadIdx.x;  // 0..BI-1
    const int b = tid >> 11;
    const int i = tid & (IQ - 1);
    const float2* ac = ((const float2*)g_AC) + tid;
    float* o = out + (size_t)b * SQ * IQ + i;

    float2 buf[SCAN_U];
#pragma unroll
    for (int u = 0; u < SCAN_U; u++) buf[u] = ac[(size_t)u * BI];

    float h = 0.0f;
    for (int t0 = 0; t0 < SQ; t0 += SCAN_U) {
        float2 nxt[SCAN_U];
        const int tn = t0 + SCAN_U;
        if (tn < SQ) {
#pragma unroll
            for (int u = 0; u < SCAN_U; u++) nxt[u] = ac[(size_t)(tn + u) * BI];
        }
#pragma unroll
        for (int u = 0; u < SCAN_U; u++) {
            h = fmaf(buf[u].x, h, buf[u].y);
            o[(size_t)(t0 + u) * IQ] = h;
        }
#pragma unroll
        for (int u = 0; u < SCAN_U; u++) buf[u] = nxt[u];
    }
}

extern "C" void kernel_launch(void* const* d_in, const int* in_sizes, int n_in,
                              void* d_out, int out_size)
{
    const float* x    = (const float*)d_in[0];
    const float* Wa   = (const float*)d_in[1];
    const float* ba   = (const float*)d_in[2];
    const float* Wi   = (const float*)d_in[3];
    const float* bi   = (const float*)d_in[4];
    const float* gate = (const float*)d_in[5];
    float* out = (float*)d_out;

    dim3 grid(IQ / BN, MQ / BM);   // (32, 128)
    gemm_gate_kernel<<<grid, 256>>>(x, Wa, ba, Wi, bi, gate);
    scan_kernel<<<BI / 128, 128>>>(out);
}

// round 11
// speedup vs baseline: 1.7525x; 1.4250x over previous
#include <cuda_runtime.h>
#include <cuda_fp16.h>
#include <math.h>

// Problem dims (fixed)
#define BQ 8
#define SQ 2048
#define DQ 512
#define IQ 2048
#define MQ (BQ * SQ)            // 16384
#define BI (BQ * IQ)            // 16384

// GEMM tiling
#define BM 128
#define BN 64
#define BK 16
// row stride in half2 units: 12*r mod 32 spans distinct bank groups -> the
// fragment loads (r in 0..7, cq in 0..3) hit 32 distinct banks.
#define XS_STRIDE 12
#define WS_STRIDE 12

// Interleaved scratch: [(s*BQ+b)*IQ + i] -> (a, c) pairs
__device__ float g_AC[(size_t)MQ * IQ * 2];

__device__ __forceinline__ unsigned pack_h2(float lo, float hi) {
    __half2 h = __floats2half2_rn(lo, hi);
    return *reinterpret_cast<unsigned*>(&h);
}

__device__ __forceinline__ float sigmoidf_fast(float v) {
    return 1.0f / (1.0f + __expf(-v));
}

__device__ __forceinline__ void mma_f16(float c[4], const unsigned a[4], const unsigned b[2]) {
    asm volatile(
        "mma.sync.aligned.m16n8k16.row.col.f32.f16.f16.f32 "
        "{%0,%1,%2,%3}, {%4,%5,%6,%7}, {%8,%9}, {%0,%1,%2,%3};\n"
        : "+f"(c[0]), "+f"(c[1]), "+f"(c[2]), "+f"(c[3])
        : "r"(a[0]), "r"(a[1]), "r"(a[2]), "r"(a[3]), "r"(b[0]), "r"(b[1]));
}

// Dual-projection fp16 tensor-core GEMM + fused gate epilogue.
// Round-6 control flow (proven 2 CTA/SM, register prefetch hides LDG under
// the MMA phase); fp16 m16n8k16 halves MMA and fragment-load issue count
// vs tf32 m16n8k8 at identical 11-bit mantissa precision.
__global__ __launch_bounds__(256)
void gemm_gate_kernel(const float* __restrict__ x,
                      const float* __restrict__ Wa,
                      const float* __restrict__ ba,
                      const float* __restrict__ Wi,
                      const float* __restrict__ bi,
                      const float* __restrict__ gate)
{
    __shared__ unsigned xs [BM * XS_STRIDE];   // 6144 B (half2-packed k-pairs)
    __shared__ unsigned was[BN * WS_STRIDE];   // 3072 B
    __shared__ unsigned wis[BN * WS_STRIDE];   // 3072 B

    const int tid    = threadIdx.x;
    const int wid    = tid >> 5;
    const int lane   = tid & 31;
    const int warp_m = wid & 3;       // 4 warps over M (4*32 = 128)
    const int warp_n = wid >> 2;      // 2 warps over N (2*32 = 64)
    const int r      = lane >> 2;     // 0..7
    const int cq     = lane & 3;      // 0..3
    const int m0     = blockIdx.y * BM;
    const int n0     = blockIdx.x * BN;

    // per-thread load slots
    const int xrow0 = tid >> 2;            // 0..63
    const int xrow1 = (tid + 256) >> 2;    // 64..127
    const int xkg   = tid & 3;             // float4 index within 16 k
    const int wrow  = tid >> 2;
    const int wkg   = tid & 3;

    float acc_a[2][4][4];
    float acc_i[2][4][4];
#pragma unroll
    for (int mt = 0; mt < 2; mt++)
#pragma unroll
        for (int nt = 0; nt < 4; nt++)
#pragma unroll
            for (int e = 0; e < 4; e++) { acc_a[mt][nt][e] = 0.f; acc_i[mt][nt][e] = 0.f; }

    // prefetch tile 0
    float4 px0 = *(const float4*)(x  + (size_t)(m0 + xrow0) * DQ + xkg * 4);
    float4 px1 = *(const float4*)(x  + (size_t)(m0 + xrow1) * DQ + xkg * 4);
    float4 pwa = *(const float4*)(Wa + (size_t)(n0 + wrow)  * DQ + wkg * 4);
    float4 pwi = *(const float4*)(Wi + (size_t)(n0 + wrow)  * DQ + wkg * 4);

    for (int kt = 0; kt < DQ; kt += BK) {
        // ---- commit prefetched regs to smem as packed half2 k-pairs ----
        {
            *(uint2*)&xs[xrow0 * XS_STRIDE + xkg * 2] =
                make_uint2(pack_h2(px0.x, px0.y), pack_h2(px0.z, px0.w));
            *(uint2*)&xs[xrow1 * XS_STRIDE + xkg * 2] =
                make_uint2(pack_h2(px1.x, px1.y), pack_h2(px1.z, px1.w));
            *(uint2*)&was[wrow * WS_STRIDE + wkg * 2] =
                make_uint2(pack_h2(pwa.x, pwa.y), pack_h2(pwa.z, pwa.w));
            *(uint2*)&wis[wrow * WS_STRIDE + wkg * 2] =
                make_uint2(pack_h2(pwi.x, pwi.y), pack_h2(pwi.z, pwi.w));
        }
        __syncthreads();

        // ---- issue next tile's global loads (hidden under MMA phase) ----
        const int ktn = kt + BK;
        if (ktn < DQ) {
            px0 = *(const float4*)(x  + (size_t)(m0 + xrow0) * DQ + ktn + xkg * 4);
            px1 = *(const float4*)(x  + (size_t)(m0 + xrow1) * DQ + ktn + xkg * 4);
            pwa = *(const float4*)(Wa + (size_t)(n0 + wrow)  * DQ + ktn + wkg * 4);
            pwi = *(const float4*)(Wi + (size_t)(n0 + wrow)  * DQ + ktn + wkg * 4);
        }

        // ---- MMA phase: single K=16 step ----
        {
            unsigned afr[2][4];
#pragma unroll
            for (int mt = 0; mt < 2; mt++) {
                const int base = warp_m * 32 + mt * 16;
                afr[mt][0] = xs[(base + r)     * XS_STRIDE + cq];
                afr[mt][1] = xs[(base + r + 8) * XS_STRIDE + cq];
                afr[mt][2] = xs[(base + r)     * XS_STRIDE + cq + 4];
                afr[mt][3] = xs[(base + r + 8) * XS_STRIDE + cq + 4];
            }
            unsigned bfa[4][2], bfi[4][2];
#pragma unroll
            for (int nt = 0; nt < 4; nt++) {
                const int nb = warp_n * 32 + nt * 8 + r;
                bfa[nt][0] = was[nb * WS_STRIDE + cq];
                bfa[nt][1] = was[nb * WS_STRIDE + cq + 4];
                bfi[nt][0] = wis[nb * WS_STRIDE + cq];
                bfi[nt][1] = wis[nb * WS_STRIDE + cq + 4];
            }
#pragma unroll
            for (int mt = 0; mt < 2; mt++)
#pragma unroll
                for (int nt = 0; nt < 4; nt++) {
                    mma_f16(acc_a[mt][nt], afr[mt], bfa[nt]);
                    mma_f16(acc_i[mt][nt], afr[mt], bfi[nt]);
                }
        }
        __syncthreads();
    }

    // ---- fused gate epilogue ----
    const float LN3 = 1.0986122886681098f;
#pragma unroll
    for (int nt = 0; nt < 4; nt++) {
        const int ich0 = n0 + warp_n * 32 + nt * 8 + 2 * cq;
        const float ba0 = __ldg(ba + ich0),     ba1 = __ldg(ba + ich0 + 1);
        const float bi0 = __ldg(bi + ich0),     bi1 = __ldg(bi + ich0 + 1);
        const float al0 = sigmoidf_fast(__ldg(gate + ich0));
        const float al1 = sigmoidf_fast(__ldg(gate + ich0 + 1));
#pragma unroll
        for (int mt = 0; mt < 2; mt++) {
#pragma unroll
            for (int ro = 0; ro < 2; ro++) {
                const int m  = m0 + warp_m * 32 + mt * 16 + r + ro * 8;
                const int bb = m >> 11;
                const int ss = m & (SQ - 1);
                const int ci = ro * 2;
                float pa0 = acc_a[mt][nt][ci]     + ba0;
                float pa1 = acc_a[mt][nt][ci + 1] + ba1;
                float pi0 = acc_i[mt][nt][ci]     + bi0;
                float pi1 = acc_i[mt][nt][ci + 1] + bi1;
                float a0 = al0 * __expf(-sigmoidf_fast(pa0) * LN3);
                float a1 = al1 * __expf(-sigmoidf_fast(pa1) * LN3);
                float c0 = sqrtf(fmaxf(1.0f - a0 * a0, 0.0f)) * sigmoidf_fast(pi0) * pi0;
                float c1 = sqrtf(fmaxf(1.0f - a1 * a1, 0.0f)) * sigmoidf_fast(pi1) * pi1;
                float4 st = make_float4(a0, c0, a1, c1);
                size_t idx = (((size_t)ss * BQ + bb) * IQ + ich0) * 2;
                *(float4*)(g_AC + idx) = st;
            }
        }
    }
}

// Sequential scan: h[t] = a*h + c. Double-buffered batches of U steps keep
// ~32 loads in flight per thread; plain loads (no cache hints).
#define SCAN_U 16
__global__ __launch_bounds__(128)
void scan_kernel(float* __restrict__ out)
{
    const int tid = blockIdx.x * blockDim.x + threadIdx.x;  // 0..BI-1
    const int b = tid >> 11;
    const int i = tid & (IQ - 1);
    const float2* ac = ((const float2*)g_AC) + tid;
    float* o = out + (size_t)b * SQ * IQ + i;

    float2 buf[SCAN_U];
#pragma unroll
    for (int u = 0; u < SCAN_U; u++) buf[u] = ac[(size_t)u * BI];

    float h = 0.0f;
    for (int t0 = 0; t0 < SQ; t0 += SCAN_U) {
        float2 nxt[SCAN_U];
        const int tn = t0 + SCAN_U;
        if (tn < SQ) {
#pragma unroll
            for (int u = 0; u < SCAN_U; u++) nxt[u] = ac[(size_t)(tn + u) * BI];
        }
#pragma unroll
        for (int u = 0; u < SCAN_U; u++) {
            h = fmaf(buf[u].x, h, buf[u].y);
            o[(size_t)(t0 + u) * IQ] = h;
        }
#pragma unroll
        for (int u = 0; u < SCAN_U; u++) buf[u] = nxt[u];
    }
}

extern "C" void kernel_launch(void* const* d_in, const int* in_sizes, int n_in,
                              void* d_out, int out_size)
{
    const float* x    = (const float*)d_in[0];
    const float* Wa   = (const float*)d_in[1];
    const float* ba   = (const float*)d_in[2];
    const float* Wi   = (const float*)d_in[3];
    const float* bi   = (const float*)d_in[4];
    const float* gate = (const float*)d_in[5];
    float* out = (float*)d_out;

    dim3 grid(IQ / BN, MQ / BM);   // (32, 128)
    gemm_gate_kernel<<<grid, 256>>>(x, Wa, ba, Wi, bi, gate);
    scan_kernel<<<BI / 128, 128>>>(out);
}